// round 5
// baseline (speedup 1.0000x reference)
#include <cuda_runtime.h>
#include <math.h>

#define N_S 1024
#define XD  128
#define HID 256

typedef unsigned long long u64;

__device__ __align__(16) float g_xpT[HID * N_S];   // xp transposed: [h][j]
__device__ __align__(16) float g_ypb[N_S * HID];   // yp + b1:       [i][h]
__device__ float g_t0[N_S];
__device__ float g_part[N_S * 2];                  // partial exp-sums [i][jhalf]

// ---------------------------------------------------------------------------
// packed f32x2 helpers (sm_103a)
// ---------------------------------------------------------------------------
__device__ __forceinline__ u64 f2add(u64 a, u64 b) {
    u64 r; asm("add.rn.f32x2 %0,%1,%2;" : "=l"(r) : "l"(a), "l"(b)); return r;
}
__device__ __forceinline__ u64 f2fma(u64 a, u64 b, u64 c) {
    u64 r; asm("fma.rn.f32x2 %0,%1,%2,%3;" : "=l"(r) : "l"(a), "l"(b), "l"(c));
    return r;
}
__device__ __forceinline__ u64 f2relu(u64 a) {
    unsigned lo, hi;
    asm("mov.b64 {%0,%1},%2;" : "=r"(lo), "=r"(hi) : "l"(a));
    float flo = fmaxf(__uint_as_float(lo), 0.f);
    float fhi = fmaxf(__uint_as_float(hi), 0.f);
    u64 r;
    asm("mov.b64 %0,{%1,%2};" : "=l"(r)
        : "r"(__float_as_uint(flo)), "r"(__float_as_uint(fhi)));
    return r;
}
__device__ __forceinline__ u64 dupf(float v) {
    unsigned u = __float_as_uint(v);
    u64 r; asm("mov.b64 %0,{%1,%1};" : "=l"(r) : "r"(u)); return r;
}
__device__ __forceinline__ void unpk(u64 a, float& lo, float& hi) {
    unsigned l, h;
    asm("mov.b64 {%0,%1},%2;" : "=r"(l), "=r"(h) : "l"(a));
    lo = __uint_as_float(l); hi = __uint_as_float(h);
}

// ---------------------------------------------------------------------------
// Projection as tiled GEMM with 4-way k-split.
// grid (4 hp-blocks, 32 row-blocks, 2 halves), block 256.
// CTA tile: 32 rows x 32 h-pairs x 128 k. Thread tile 4x4 f32x2.
// smem (dynamic 69632B): xd[128][34] dup pairs, ws[128][34] true W pairs.
// ---------------------------------------------------------------------------
#define PJ_STR 34
#define PJ_SMEM_U64 (2 * 128 * PJ_STR)

__global__ void __launch_bounds__(256) proj_kernel(const float* __restrict__ x,
                                                   const float* __restrict__ y,
                                                   const float* __restrict__ W1,
                                                   const float* __restrict__ b1) {
    extern __shared__ u64 sraw[];
    u64* xd = sraw;                  // [128][PJ_STR]
    u64* ws = sraw + 128 * PJ_STR;   // [128][PJ_STR]

    const int t    = threadIdx.x;
    const int hb   = blockIdx.x * 32;     // h-pair base (0..96)
    const int rb   = blockIdx.y * 32;     // row base
    const int half = blockIdx.z;
    const float* src = (half == 0) ? x : y;
    const float* Wh  = W1 + half * XD * HID;

    // stage x rows as dup pairs: xd[k][r]
    #pragma unroll
    for (int c = 0; c < 4; c++) {
        const int lin = t + 256 * c;        // 0..1023
        const int r   = lin >> 5;           // 0..31
        const int k4  = lin & 31;           // float4 column
        const float4 v = *reinterpret_cast<const float4*>(
            src + (rb + r) * XD + k4 * 4);
        xd[(k4 * 4 + 0) * PJ_STR + r] = dupf(v.x);
        xd[(k4 * 4 + 1) * PJ_STR + r] = dupf(v.y);
        xd[(k4 * 4 + 2) * PJ_STR + r] = dupf(v.z);
        xd[(k4 * 4 + 3) * PJ_STR + r] = dupf(v.w);
    }
    // stage W true pairs: ws[k][i], i = local h-pair
    const ulonglong2* Wp = reinterpret_cast<const ulonglong2*>(Wh); // [k][64]
    #pragma unroll
    for (int c = 0; c < 8; c++) {
        const int lin = t + 256 * c;        // 0..2047
        const int k   = lin >> 4;
        const int i2  = lin & 15;           // ulonglong2 index (2 pairs)
        const ulonglong2 v = Wp[k * 64 + (hb >> 1) + i2];
        *reinterpret_cast<ulonglong2*>(&ws[k * PJ_STR + i2 * 2]) = v;
    }
    __syncthreads();

    const int kg = t >> 6;                  // k-group 0..3
    const int u  = t & 63;
    const int tr = ((u >> 3) & 7) * 4;      // row sub-base 0..28
    const int th = (u & 7) * 4;             // hp sub-base 0..28

    u64 acc[4][4];
    #pragma unroll
    for (int r = 0; r < 4; r++)
        #pragma unroll
        for (int c = 0; c < 4; c++) acc[r][c] = 0ull;

    const int k0 = kg * 32;
    #pragma unroll 8
    for (int k = k0; k < k0 + 32; k++) {
        const ulonglong2 xa = *reinterpret_cast<const ulonglong2*>(
            &xd[k * PJ_STR + tr]);
        const ulonglong2 xb = *reinterpret_cast<const ulonglong2*>(
            &xd[k * PJ_STR + tr + 2]);
        const ulonglong2 wa = *reinterpret_cast<const ulonglong2*>(
            &ws[k * PJ_STR + th]);
        const ulonglong2 wb = *reinterpret_cast<const ulonglong2*>(
            &ws[k * PJ_STR + th + 2]);
        const u64 lx[4] = {xa.x, xa.y, xb.x, xb.y};
        const u64 lw[4] = {wa.x, wa.y, wb.x, wb.y};
        #pragma unroll
        for (int r = 0; r < 4; r++)
            #pragma unroll
            for (int c = 0; c < 4; c++)
                acc[r][c] = f2fma(lx[r], lw[c], acc[r][c]);
    }
    __syncthreads();

    // k-split partials -> smem (stride 17 to spread banks), then reduce.
    u64* buf = sraw;
    #pragma unroll
    for (int r = 0; r < 4; r++)
        #pragma unroll
        for (int c = 0; c < 4; c++)
            buf[t * 17 + r * 4 + c] = acc[r][c];
    __syncthreads();

    if (half == 0) {
        // layout: r = t&31 (coalesced column stores into g_xpT)
        #pragma unroll
        for (int q = 0; q < 4; q++) {
            const int r = t & 31;
            const int c = (t >> 5) + 8 * q;
            u64 s = 0ull;
            #pragma unroll
            for (int kgi = 0; kgi < 4; kgi++) {
                const int thr = kgi * 64 + (r >> 2) * 8 + (c >> 2);
                s = f2add(s, buf[thr * 17 + (r & 3) * 4 + (c & 3)]);
            }
            float lo, hi; unpk(s, lo, hi);
            const int H = hb + c;
            g_xpT[(2 * H) * N_S + rb + r]     = lo;
            g_xpT[(2 * H + 1) * N_S + rb + r] = hi;
        }
    } else {
        const u64* b1p = reinterpret_cast<const u64*>(b1);
        #pragma unroll
        for (int q = 0; q < 4; q++) {
            const int o = t * 4 + q;
            const int r = o >> 5;
            const int c = o & 31;
            u64 s = 0ull;
            #pragma unroll
            for (int kgi = 0; kgi < 4; kgi++) {
                const int thr = kgi * 64 + (r >> 2) * 8 + (c >> 2);
                s = f2add(s, buf[thr * 17 + (r & 3) * 4 + (c & 3)]);
            }
            const int H = hb + c;
            *reinterpret_cast<u64*>(&g_ypb[(rb + r) * HID + 2 * H]) =
                f2add(s, b1p[H]);
        }
    }
}

// ---------------------------------------------------------------------------
// Main: T1[i,j] = sum_h relu(ypb[i,h] + xp[j,h]) * W2[h]  (+b2 in epilogue)
// grid (64 i-blocks x 2 j-halves), block 512. CTA: 16 rows x 512 j.
// Thread: 4 j (one LDG.128) x 4 rows (group g = t>>7) = 16 elements/h.
// ---------------------------------------------------------------------------
__global__ void __launch_bounds__(512) main_kernel(const float* __restrict__ W2,
                                                   const float* __restrict__ b2) {
    __shared__ __align__(16) u64 s_y[HID][18];   // dup pairs, padded stride
    __shared__ u64 s_w[HID];                     // dup pairs
    __shared__ float red[64];                    // [row16][4 warps-in-group]

    const int t  = threadIdx.x;
    const int ib = blockIdx.x * 16;
    const int jh = blockIdx.y;

    for (int idx = t; idx < HID * 16; idx += 512) {
        const int slot = idx >> 8;               // 0..15 (row)
        const int h    = idx & 255;
        s_y[h][slot] = dupf(g_ypb[(ib + slot) * HID + h]);
    }
    if (t < HID) s_w[t] = dupf(W2[t]);
    __syncthreads();

    const int tj = t & 127;
    const int g  = t >> 7;                       // row group 0..3
    const ulonglong2* XP =
        reinterpret_cast<const ulonglong2*>(g_xpT) + jh * 128 + tj; // +256/h

    u64 acc[4][2];
    #pragma unroll
    for (int i = 0; i < 4; i++) { acc[i][0] = 0ull; acc[i][1] = 0ull; }

    ulonglong2 ring[4];
    #pragma unroll
    for (int p = 0; p < 4; p++) ring[p] = XP[p * 256];

    for (int hb = 0; hb < HID; hb += 4) {
        #pragma unroll
        for (int p = 0; p < 4; p++) {
            const int h = hb + p;
            const ulonglong2 xx = ring[p];
            if (hb < HID - 4) ring[p] = XP[(h + 4) * 256];
            const u64 ww = s_w[h];
            const ulonglong2 ya =
                *reinterpret_cast<const ulonglong2*>(&s_y[h][g * 4]);
            const ulonglong2 yb =
                *reinterpret_cast<const ulonglong2*>(&s_y[h][g * 4 + 2]);
            const u64 yv[4] = {ya.x, ya.y, yb.x, yb.y};
            #pragma unroll
            for (int i = 0; i < 4; i++) {
                acc[i][0] = f2fma(f2relu(f2add(yv[i], xx.x)), ww, acc[i][0]);
                acc[i][1] = f2fma(f2relu(f2add(yv[i], xx.y)), ww, acc[i][1]);
            }
        }
    }

    // Epilogue
    const float b2v = b2[0];
    const int lane = t & 31;
    const int wg   = (t >> 5) & 3;               // warp index within group
    const int jb   = jh * 512 + tj * 4;

    #pragma unroll
    for (int i = 0; i < 4; i++) {
        const int rloc = g * 4 + i;
        const int ig   = ib + rloc;
        float v[4];
        unpk(acc[i][0], v[0], v[1]);
        unpk(acc[i][1], v[2], v[3]);
        float s = 0.f;
        #pragma unroll
        for (int c = 0; c < 4; c++) {
            v[c] += b2v;
            if (jb + c == ig) g_t0[ig] = v[c];   // diagonal T0
            s += __expf(v[c]);
        }
        #pragma unroll
        for (int o = 16; o > 0; o >>= 1) s += __shfl_xor_sync(0xffffffffu, s, o);
        if (lane == 0) red[rloc * 4 + wg] = s;
    }
    __syncthreads();

    if (t < 64) {
        const int row = t >> 2;
        float v = red[t];
        v += __shfl_xor_sync(0xffffffffu, v, 1);
        v += __shfl_xor_sync(0xffffffffu, v, 2);
        if ((t & 3) == 0) g_part[(ib + row) * 2 + jh] = v;
    }
}

// ---------------------------------------------------------------------------
// Finalize: lb = mean(T0) - (mean(log(part0+part1)) - log(N))
// ---------------------------------------------------------------------------
__global__ void __launch_bounds__(256) finalize_kernel(float* __restrict__ out) {
    __shared__ float r1[256], r2[256];
    const int t = threadIdx.x;
    float a = 0.f, b = 0.f;
    #pragma unroll
    for (int p = 0; p < 4; p++) {
        const int i = t + 256 * p;
        a += g_t0[i];
        b += logf(g_part[2 * i] + g_part[2 * i + 1]);
    }
    r1[t] = a; r2[t] = b;
    __syncthreads();
    for (int off = 128; off > 0; off >>= 1) {
        if (t < off) { r1[t] += r1[t + off]; r2[t] += r2[t + off]; }
        __syncthreads();
    }
    if (t == 0) {
        out[0] = r1[0] / (float)N_S - (r2[0] / (float)N_S - logf((float)N_S));
    }
}

// ---------------------------------------------------------------------------
extern "C" void kernel_launch(void* const* d_in, const int* in_sizes, int n_in,
                              void* d_out, int out_size) {
    const float* x  = (const float*)d_in[0];
    const float* y  = (const float*)d_in[1];
    const float* W1 = (const float*)d_in[2];
    const float* b1 = (const float*)d_in[3];
    const float* W2 = (const float*)d_in[4];
    const float* b2 = (const float*)d_in[5];

    const int pj_smem = PJ_SMEM_U64 * 8;   // 69632 bytes
    cudaFuncSetAttribute(proj_kernel,
                         cudaFuncAttributeMaxDynamicSharedMemorySize, pj_smem);

    proj_kernel<<<dim3(4, 32, 2), 256, pj_smem>>>(x, y, W1, b1);
    main_kernel<<<dim3(64, 2), 512>>>(W2, b2);
    finalize_kernel<<<1, 256>>>((float*)d_out);
}

// round 6
// speedup vs baseline: 1.2482x; 1.2482x over previous
#include <cuda_runtime.h>
#include <math.h>

#define N_S 1024
#define XD  128
#define HID 256

typedef unsigned long long u64;

__device__ __align__(16) float g_xpT[HID * N_S];   // xp transposed: [h][j]
__device__ __align__(16) float g_ypb[N_S * HID];   // yp + b1:       [i][h]
__device__ float g_t0[N_S];
__device__ float g_part[N_S * 2];                  // partial exp-sums [i][jhalf]

// ---------------------------------------------------------------------------
// packed f32x2 helpers (sm_103a)
// ---------------------------------------------------------------------------
__device__ __forceinline__ u64 f2add(u64 a, u64 b) {
    u64 r; asm("add.rn.f32x2 %0,%1,%2;" : "=l"(r) : "l"(a), "l"(b)); return r;
}
__device__ __forceinline__ u64 f2fma(u64 a, u64 b, u64 c) {
    u64 r; asm("fma.rn.f32x2 %0,%1,%2,%3;" : "=l"(r) : "l"(a), "l"(b), "l"(c));
    return r;
}
__device__ __forceinline__ u64 f2relu(u64 a) {
    unsigned lo, hi;
    asm("mov.b64 {%0,%1},%2;" : "=r"(lo), "=r"(hi) : "l"(a));
    float flo = fmaxf(__uint_as_float(lo), 0.f);
    float fhi = fmaxf(__uint_as_float(hi), 0.f);
    u64 r;
    asm("mov.b64 %0,{%1,%2};" : "=l"(r)
        : "r"(__float_as_uint(flo)), "r"(__float_as_uint(fhi)));
    return r;
}
__device__ __forceinline__ u64 dupf(float v) {
    unsigned u = __float_as_uint(v);
    u64 r; asm("mov.b64 %0,{%1,%1};" : "=l"(r) : "r"(u)); return r;
}
__device__ __forceinline__ void unpk(u64 a, float& lo, float& hi) {
    unsigned l, h;
    asm("mov.b64 {%0,%1},%2;" : "=r"(l), "=r"(h) : "l"(a));
    lo = __uint_as_float(l); hi = __uint_as_float(h);
}

// ---------------------------------------------------------------------------
// Projection as tiled GEMM, full-k per thread (NO k-split).
// grid (4 hp-blocks, 32 row-blocks, 2 halves) = 256 CTAs, block 256.
// CTA tile: 32 rows x 32 h-pairs x 128 k. Thread tile 2x2 f32x2, k=128.
// smem (dynamic 69632B): xd[128][34] dup pairs, ws[128][34] true W pairs.
// ---------------------------------------------------------------------------
#define PJX 34
#define PJ_SMEM_BYTES (2 * 128 * PJX * 8)

__global__ void __launch_bounds__(256) proj_kernel(const float* __restrict__ x,
                                                   const float* __restrict__ y,
                                                   const float* __restrict__ W1,
                                                   const float* __restrict__ b1) {
    extern __shared__ u64 sraw[];
    u64* xd = sraw;               // [128][PJX] x rows as dup pairs
    u64* ws = sraw + 128 * PJX;   // [128][PJX] W true pairs

    const int t    = threadIdx.x;
    const int hb   = blockIdx.x * 32;     // h-pair base (0,32,64,96)
    const int rb   = blockIdx.y * 32;     // row base
    const int half = blockIdx.z;
    const float* src = (half == 0) ? x : y;
    const float* Wh  = W1 + half * XD * HID;

    // stage x rows as dup pairs: xd[k][r]
    #pragma unroll
    for (int c = 0; c < 4; c++) {
        const int lin = t + 256 * c;        // 0..1023
        const int r   = lin >> 5;           // 0..31
        const int k4  = lin & 31;           // float4 column
        const float4 v = *reinterpret_cast<const float4*>(
            src + (rb + r) * XD + k4 * 4);
        xd[(k4 * 4 + 0) * PJX + r] = dupf(v.x);
        xd[(k4 * 4 + 1) * PJX + r] = dupf(v.y);
        xd[(k4 * 4 + 2) * PJX + r] = dupf(v.z);
        xd[(k4 * 4 + 3) * PJX + r] = dupf(v.w);
    }
    // stage W true pairs: ws[k][c], c = local h-pair 0..31
    const ulonglong2* Wp = reinterpret_cast<const ulonglong2*>(Wh); // [k][64]
    #pragma unroll
    for (int c = 0; c < 8; c++) {
        const int lin = t + 256 * c;        // 0..2047
        const int k   = lin >> 4;
        const int i2  = lin & 15;           // pair-pair index
        const ulonglong2 v = Wp[k * 64 + (hb >> 1) + i2];
        *reinterpret_cast<ulonglong2*>(&ws[k * PJX + i2 * 2]) = v;
    }
    __syncthreads();

    const int tr = ((t >> 4) & 15) * 2;     // row sub-base 0..30
    const int th = (t & 15) * 2;            // hp  sub-base 0..30

    u64 a00 = 0ull, a01 = 0ull, a10 = 0ull, a11 = 0ull;

    #pragma unroll 8
    for (int k = 0; k < XD; k++) {
        const ulonglong2 xv =
            *reinterpret_cast<const ulonglong2*>(&xd[k * PJX + tr]);
        const ulonglong2 wv =
            *reinterpret_cast<const ulonglong2*>(&ws[k * PJX + th]);
        a00 = f2fma(xv.x, wv.x, a00);
        a01 = f2fma(xv.x, wv.y, a01);
        a10 = f2fma(xv.y, wv.x, a10);
        a11 = f2fma(xv.y, wv.y, a11);
    }

    if (half == 0) {
        float lo, hi;
        const int H0 = hb + th, H1 = hb + th + 1;
        const int r0 = rb + tr, r1 = rb + tr + 1;
        unpk(a00, lo, hi);
        g_xpT[(2 * H0) * N_S + r0] = lo; g_xpT[(2 * H0 + 1) * N_S + r0] = hi;
        unpk(a01, lo, hi);
        g_xpT[(2 * H1) * N_S + r0] = lo; g_xpT[(2 * H1 + 1) * N_S + r0] = hi;
        unpk(a10, lo, hi);
        g_xpT[(2 * H0) * N_S + r1] = lo; g_xpT[(2 * H0 + 1) * N_S + r1] = hi;
        unpk(a11, lo, hi);
        g_xpT[(2 * H1) * N_S + r1] = lo; g_xpT[(2 * H1 + 1) * N_S + r1] = hi;
    } else {
        const u64* b1p = reinterpret_cast<const u64*>(b1);
        const int H0 = hb + th, H1 = hb + th + 1;
        const int r0 = rb + tr, r1 = rb + tr + 1;
        const u64 bb0 = b1p[H0], bb1 = b1p[H1];
        *reinterpret_cast<u64*>(&g_ypb[r0 * HID + 2 * H0]) = f2add(a00, bb0);
        *reinterpret_cast<u64*>(&g_ypb[r0 * HID + 2 * H1]) = f2add(a01, bb1);
        *reinterpret_cast<u64*>(&g_ypb[r1 * HID + 2 * H0]) = f2add(a10, bb0);
        *reinterpret_cast<u64*>(&g_ypb[r1 * HID + 2 * H1]) = f2add(a11, bb1);
    }
}

// ---------------------------------------------------------------------------
// Main (reverted to the measured-good R4 structure):
// T1[i,j] = sum_h relu(ypb[i,h] + xp[j,h]) * W2[h]
// grid 148 = 74 i-blocks (62x14 rows + 12x13) x 2 j-halves (512 j each).
// block 512: group g=t>>8 handles 7 rows; thread owns one j-pair (f32x2).
// ---------------------------------------------------------------------------
__global__ void __launch_bounds__(512) main_kernel(const float* __restrict__ W2,
                                                   const float* __restrict__ b2) {
    __shared__ __align__(16) u64 s_y[2][HID][8];
    __shared__ __align__(16) u64 s_w[HID];
    __shared__ float red[112];

    const int t   = threadIdx.x;
    const int ibk = blockIdx.x >> 1;
    const int jh  = blockIdx.x & 1;
    const int nrows = (ibk < 62) ? 14 : 13;
    const int ib    = (ibk < 62) ? ibk * 14 : 868 + (ibk - 62) * 13;

    const int g  = t >> 8;
    const int tt = t & 255;
    const int jp = (jh << 8) + tt;
    const int j0 = 2 * jp;

    for (int idx = t; idx < HID * 16; idx += 512) {
        const int h  = idx & 255;
        const int sl = idx >> 8;
        const int sg = sl >> 3, si = sl & 7;
        int row = sg * 7 + (si < 7 ? si : 6);
        if (row > nrows - 1) row = nrows - 1;
        s_y[sg][h][si] = dupf(g_ypb[(ib + row) * HID + h]);
    }
    if (t < HID) s_w[t] = dupf(W2[t]);
    __syncthreads();

    u64 acc[7];
    #pragma unroll
    for (int i = 0; i < 7; i++) acc[i] = 0ull;

    const u64* xp = reinterpret_cast<const u64*>(g_xpT) + jp;

    u64 xb[8];
    #pragma unroll
    for (int p = 0; p < 8; p++) xb[p] = xp[p * 512];

    for (int hb = 0; hb < HID; hb += 8) {
        #pragma unroll
        for (int p = 0; p < 8; p++) {
            const int h = hb + p;
            const u64 xx = xb[p];
            if (hb < HID - 8) xb[p] = xp[(h + 8) * 512];
            const u64 ww = s_w[h];
            const u64* yrow = s_y[g][h];
            const ulonglong2 ya = *reinterpret_cast<const ulonglong2*>(&yrow[0]);
            const ulonglong2 yc = *reinterpret_cast<const ulonglong2*>(&yrow[2]);
            const ulonglong2 ye = *reinterpret_cast<const ulonglong2*>(&yrow[4]);
            const u64 y6 = yrow[6];
            acc[0] = f2fma(f2relu(f2add(ya.x, xx)), ww, acc[0]);
            acc[1] = f2fma(f2relu(f2add(ya.y, xx)), ww, acc[1]);
            acc[2] = f2fma(f2relu(f2add(yc.x, xx)), ww, acc[2]);
            acc[3] = f2fma(f2relu(f2add(yc.y, xx)), ww, acc[3]);
            acc[4] = f2fma(f2relu(f2add(ye.x, xx)), ww, acc[4]);
            acc[5] = f2fma(f2relu(f2add(ye.y, xx)), ww, acc[5]);
            acc[6] = f2fma(f2relu(f2add(y6,   xx)), ww, acc[6]);
        }
    }

    const float b2v = b2[0];
    const int lane = t & 31;
    const int wrp  = (t >> 5) & 7;

    #pragma unroll
    for (int i = 0; i < 7; i++) {
        const int rloc = g * 7 + i;
        const int ig   = ib + rloc;
        const bool valid = (g == 0) || (i < nrows - 7);
        float v0, v1;
        unpk(acc[i], v0, v1);
        v0 += b2v; v1 += b2v;
        if (valid) {
            if (j0     == ig) g_t0[ig] = v0;
            if (j0 + 1 == ig) g_t0[ig] = v1;
        }
        float s = valid ? (__expf(v0) + __expf(v1)) : 0.f;
        #pragma unroll
        for (int o = 16; o > 0; o >>= 1) s += __shfl_xor_sync(0xffffffffu, s, o);
        if (lane == 0) red[rloc * 8 + wrp] = s;
    }
    __syncthreads();

    if (t < 112) {
        const int row = t >> 3;
        float v = red[t];
        #pragma unroll
        for (int o = 4; o > 0; o >>= 1) v += __shfl_xor_sync(0xffffffffu, v, o);
        if ((t & 7) == 0 && row < nrows) {
            g_part[(ib + row) * 2 + jh] = v;
        }
    }
}

// ---------------------------------------------------------------------------
// Finalize: lb = mean(T0) - (mean(log(part0+part1)) - log(N))
// ---------------------------------------------------------------------------
__global__ void __launch_bounds__(256) finalize_kernel(float* __restrict__ out) {
    __shared__ float r1[256], r2[256];
    const int t = threadIdx.x;
    float a = 0.f, b = 0.f;
    #pragma unroll
    for (int p = 0; p < 4; p++) {
        const int i = t + 256 * p;
        a += g_t0[i];
        b += logf(g_part[2 * i] + g_part[2 * i + 1]);
    }
    r1[t] = a; r2[t] = b;
    __syncthreads();
    for (int off = 128; off > 0; off >>= 1) {
        if (t < off) { r1[t] += r1[t + off]; r2[t] += r2[t + off]; }
        __syncthreads();
    }
    if (t == 0) {
        out[0] = r1[0] / (float)N_S - (r2[0] / (float)N_S - logf((float)N_S));
    }
}

// ---------------------------------------------------------------------------
extern "C" void kernel_launch(void* const* d_in, const int* in_sizes, int n_in,
                              void* d_out, int out_size) {
    const float* x  = (const float*)d_in[0];
    const float* y  = (const float*)d_in[1];
    const float* W1 = (const float*)d_in[2];
    const float* b1 = (const float*)d_in[3];
    const float* W2 = (const float*)d_in[4];
    const float* b2 = (const float*)d_in[5];

    cudaFuncSetAttribute(proj_kernel,
                         cudaFuncAttributeMaxDynamicSharedMemorySize,
                         PJ_SMEM_BYTES);

    proj_kernel<<<dim3(4, 32, 2), 256, PJ_SMEM_BYTES>>>(x, y, W1, b1);
    main_kernel<<<148, 512>>>(W2, b2);
    finalize_kernel<<<1, 256>>>((float*)d_out);
}

// round 8
// speedup vs baseline: 1.2941x; 1.0368x over previous
#include <cuda_runtime.h>
#include <math.h>

#define N_S 1024
#define XD  128
#define HID 256
#define MAIN_CTAS 296

typedef unsigned long long u64;

__device__ __align__(16) float g_xpT[HID * N_S];   // xp transposed: [h][j]
__device__ __align__(16) float g_ypb[N_S * HID];   // yp + b1:       [i][h]
__device__ float g_t0[N_S];
__device__ __align__(16) float g_part[N_S * 4];    // partial exp-sums [i][jq]
__device__ unsigned g_done;                        // ticket (zero-init, self-reset)

// ---------------------------------------------------------------------------
// packed f32x2 helpers (sm_103a)
// ---------------------------------------------------------------------------
__device__ __forceinline__ u64 f2add(u64 a, u64 b) {
    u64 r; asm("add.rn.f32x2 %0,%1,%2;" : "=l"(r) : "l"(a), "l"(b)); return r;
}
__device__ __forceinline__ u64 f2fma(u64 a, u64 b, u64 c) {
    u64 r; asm("fma.rn.f32x2 %0,%1,%2,%3;" : "=l"(r) : "l"(a), "l"(b), "l"(c));
    return r;
}
__device__ __forceinline__ u64 f2relu(u64 a) {
    unsigned lo, hi;
    asm("mov.b64 {%0,%1},%2;" : "=r"(lo), "=r"(hi) : "l"(a));
    float flo = fmaxf(__uint_as_float(lo), 0.f);
    float fhi = fmaxf(__uint_as_float(hi), 0.f);
    u64 r;
    asm("mov.b64 %0,{%1,%2};" : "=l"(r)
        : "r"(__float_as_uint(flo)), "r"(__float_as_uint(fhi)));
    return r;
}
__device__ __forceinline__ u64 dupf(float v) {
    unsigned u = __float_as_uint(v);
    u64 r; asm("mov.b64 %0,{%1,%1};" : "=l"(r) : "r"(u)); return r;
}
__device__ __forceinline__ void unpk(u64 a, float& lo, float& hi) {
    unsigned l, h;
    asm("mov.b64 {%0,%1},%2;" : "=r"(l), "=r"(h) : "l"(a));
    lo = __uint_as_float(l); hi = __uint_as_float(h);
}

// ---------------------------------------------------------------------------
// Projection (R6 structure + explicit depth-4 LDS prefetch ring).
// grid (4 hp-blocks, 32 row-blocks, 2 halves) = 256 CTAs, block 256.
// ---------------------------------------------------------------------------
#define PJX 34
#define PJ_SMEM_BYTES (2 * 128 * PJX * 8)

__global__ void __launch_bounds__(256) proj_kernel(const float* __restrict__ x,
                                                   const float* __restrict__ y,
                                                   const float* __restrict__ W1,
                                                   const float* __restrict__ b1) {
    extern __shared__ u64 sraw[];
    u64* xd = sraw;               // [128][PJX] x rows as dup pairs
    u64* ws = sraw + 128 * PJX;   // [128][PJX] W true pairs

    const int t    = threadIdx.x;
    const int hb   = blockIdx.x * 32;
    const int rb   = blockIdx.y * 32;
    const int half = blockIdx.z;
    const float* src = (half == 0) ? x : y;
    const float* Wh  = W1 + half * XD * HID;

    #pragma unroll
    for (int c = 0; c < 4; c++) {
        const int lin = t + 256 * c;
        const int r   = lin >> 5;
        const int k4  = lin & 31;
        const float4 v = *reinterpret_cast<const float4*>(
            src + (rb + r) * XD + k4 * 4);
        xd[(k4 * 4 + 0) * PJX + r] = dupf(v.x);
        xd[(k4 * 4 + 1) * PJX + r] = dupf(v.y);
        xd[(k4 * 4 + 2) * PJX + r] = dupf(v.z);
        xd[(k4 * 4 + 3) * PJX + r] = dupf(v.w);
    }
    const ulonglong2* Wp = reinterpret_cast<const ulonglong2*>(Wh);
    #pragma unroll
    for (int c = 0; c < 8; c++) {
        const int lin = t + 256 * c;
        const int k   = lin >> 4;
        const int i2  = lin & 15;
        const ulonglong2 v = Wp[k * 64 + (hb >> 1) + i2];
        *reinterpret_cast<ulonglong2*>(&ws[k * PJX + i2 * 2]) = v;
    }
    __syncthreads();

    const int tr = ((t >> 4) & 15) * 2;
    const int th = (t & 15) * 2;

    u64 a00 = 0ull, a01 = 0ull, a10 = 0ull, a11 = 0ull;

    // explicit depth-4 LDS prefetch ring
    ulonglong2 xr[4], wr[4];
    #pragma unroll
    for (int q = 0; q < 4; q++) {
        xr[q] = *reinterpret_cast<const ulonglong2*>(&xd[q * PJX + tr]);
        wr[q] = *reinterpret_cast<const ulonglong2*>(&ws[q * PJX + th]);
    }

    for (int kb = 0; kb < XD; kb += 4) {
        #pragma unroll
        for (int q = 0; q < 4; q++) {
            const ulonglong2 xv = xr[q];
            const ulonglong2 wv = wr[q];
            if (kb < XD - 4) {
                xr[q] = *reinterpret_cast<const ulonglong2*>(
                    &xd[(kb + 4 + q) * PJX + tr]);
                wr[q] = *reinterpret_cast<const ulonglong2*>(
                    &ws[(kb + 4 + q) * PJX + th]);
            }
            a00 = f2fma(xv.x, wv.x, a00);
            a01 = f2fma(xv.x, wv.y, a01);
            a10 = f2fma(xv.y, wv.x, a10);
            a11 = f2fma(xv.y, wv.y, a11);
        }
    }

    if (half == 0) {
        float lo, hi;
        const int H0 = hb + th, H1 = hb + th + 1;
        const int r0 = rb + tr, r1 = rb + tr + 1;
        unpk(a00, lo, hi);
        g_xpT[(2 * H0) * N_S + r0] = lo; g_xpT[(2 * H0 + 1) * N_S + r0] = hi;
        unpk(a01, lo, hi);
        g_xpT[(2 * H1) * N_S + r0] = lo; g_xpT[(2 * H1 + 1) * N_S + r0] = hi;
        unpk(a10, lo, hi);
        g_xpT[(2 * H0) * N_S + r1] = lo; g_xpT[(2 * H0 + 1) * N_S + r1] = hi;
        unpk(a11, lo, hi);
        g_xpT[(2 * H1) * N_S + r1] = lo; g_xpT[(2 * H1 + 1) * N_S + r1] = hi;
    } else {
        const u64* b1p = reinterpret_cast<const u64*>(b1);
        const int H0 = hb + th, H1 = hb + th + 1;
        const int r0 = rb + tr, r1 = rb + tr + 1;
        const u64 bb0 = b1p[H0], bb1 = b1p[H1];
        *reinterpret_cast<u64*>(&g_ypb[r0 * HID + 2 * H0]) = f2add(a00, bb0);
        *reinterpret_cast<u64*>(&g_ypb[r0 * HID + 2 * H1]) = f2add(a01, bb1);
        *reinterpret_cast<u64*>(&g_ypb[r1 * HID + 2 * H0]) = f2add(a10, bb0);
        *reinterpret_cast<u64*>(&g_ypb[r1 * HID + 2 * H1]) = f2add(a11, bb1);
    }
}

// ---------------------------------------------------------------------------
// Main: T1[i,j] = sum_h relu(ypb[i,h] + xp[j,h]) * W2[h]
// grid 296 = 74 i-blocks (62x14 / 12x13 rows) x 4 j-quarters, block 256.
// s_y slot 7 holds dup(W2[h]) -> one LDS.128 serves y6+w. Last CTA finalizes.
// ---------------------------------------------------------------------------
__global__ void __launch_bounds__(256) main_kernel(const float* __restrict__ W2,
                                                   const float* __restrict__ b2,
                                                   float* __restrict__ out) {
    __shared__ __align__(16) u64 s_y[2][HID][8];   // [g][h][slot]; slot7 = W2 dup
    __shared__ float red[56];
    __shared__ unsigned s_ticket;

    const int t   = threadIdx.x;
    const int ibk = blockIdx.x >> 2;             // i-block 0..73
    const int jq  = blockIdx.x & 3;              // j-quarter
    const int nrows = (ibk < 62) ? 14 : 13;
    const int ib    = (ibk < 62) ? ibk * 14 : 868 + (ibk - 62) * 13;

    const int g  = t >> 7;                       // row group 0/1
    const int tt = t & 127;
    const int jp = (jq << 7) + tt;               // j-pair index 0..511
    const int j0 = 2 * jp;

    // coalesced staging: word w = sg*2048 + h*8 + si
    #pragma unroll
    for (int it = 0; it < 16; it++) {
        const int w   = t + 256 * it;
        const int sg  = w >> 11;
        const int rem = w & 2047;
        const int h   = rem >> 3;
        const int si  = rem & 7;
        u64 val;
        if (si == 7) {
            val = dupf(W2[h]);
        } else {
            int row = sg * 7 + si;
            if (row > nrows - 1) row = nrows - 1;
            val = dupf(g_ypb[(ib + row) * HID + h]);
        }
        s_y[sg][h][si] = val;
    }
    __syncthreads();

    u64 acc[7];
    #pragma unroll
    for (int i = 0; i < 7; i++) acc[i] = 0ull;

    const u64* xp = reinterpret_cast<const u64*>(g_xpT) + jp;

    u64 xb[8];
    #pragma unroll
    for (int p = 0; p < 8; p++) xb[p] = xp[p * 512];

    for (int hb = 0; hb < HID; hb += 8) {
        #pragma unroll
        for (int p = 0; p < 8; p++) {
            const int h = hb + p;
            const u64 xx = xb[p];
            if (hb < HID - 8) xb[p] = xp[(h + 8) * 512];
            const u64* yrow = s_y[g][h];
            const ulonglong2 ya = *reinterpret_cast<const ulonglong2*>(&yrow[0]);
            const ulonglong2 yc = *reinterpret_cast<const ulonglong2*>(&yrow[2]);
            const ulonglong2 ye = *reinterpret_cast<const ulonglong2*>(&yrow[4]);
            const ulonglong2 yz = *reinterpret_cast<const ulonglong2*>(&yrow[6]);
            const u64 ww = yz.y;
            acc[0] = f2fma(f2relu(f2add(ya.x, xx)), ww, acc[0]);
            acc[1] = f2fma(f2relu(f2add(ya.y, xx)), ww, acc[1]);
            acc[2] = f2fma(f2relu(f2add(yc.x, xx)), ww, acc[2]);
            acc[3] = f2fma(f2relu(f2add(yc.y, xx)), ww, acc[3]);
            acc[4] = f2fma(f2relu(f2add(ye.x, xx)), ww, acc[4]);
            acc[5] = f2fma(f2relu(f2add(ye.y, xx)), ww, acc[5]);
            acc[6] = f2fma(f2relu(f2add(yz.x, xx)), ww, acc[6]);
        }
    }

    const float b2v = b2[0];
    const int lane = t & 31;
    const int wrp  = (t >> 5) & 3;               // warp within group

    #pragma unroll
    for (int i = 0; i < 7; i++) {
        const int rloc = g * 7 + i;
        const int ig   = ib + rloc;
        const bool valid = (g == 0) || (i < nrows - 7);
        float v0, v1;
        unpk(acc[i], v0, v1);
        v0 += b2v; v1 += b2v;
        if (valid) {
            if (j0     == ig) g_t0[ig] = v0;
            if (j0 + 1 == ig) g_t0[ig] = v1;
        }
        float s = valid ? (__expf(v0) + __expf(v1)) : 0.f;
        #pragma unroll
        for (int o = 16; o > 0; o >>= 1) s += __shfl_xor_sync(0xffffffffu, s, o);
        if (lane == 0) red[rloc * 4 + wrp] = s;
    }
    __syncthreads();

    if (t < 64) {
        const int row = t >> 2;                  // 0..15
        float v = (t < 56) ? red[t] : 0.f;
        v += __shfl_xor_sync(0xffffffffu, v, 1);
        v += __shfl_xor_sync(0xffffffffu, v, 2);
        if ((t & 3) == 0 && row < nrows) {
            g_part[(ib + row) * 4 + jq] = v;
        }
    }

    // ---- last-CTA finalize ----
    __threadfence();
    __syncthreads();
    if (t == 0) s_ticket = atomicAdd(&g_done, 1u);
    __syncthreads();
    if (s_ticket == MAIN_CTAS - 1) {
        float* fb = reinterpret_cast<float*>(&s_y[0][0][0]);
        float a = 0.f, b = 0.f;
        #pragma unroll
        for (int p = 0; p < 4; p++) {
            const int i = t + 256 * p;
            const float4 q = *reinterpret_cast<const float4*>(&g_part[4 * i]);
            a += g_t0[i];
            b += logf(q.x + q.y + q.z + q.w);
        }
        fb[t] = a; fb[256 + t] = b;
        __syncthreads();
        for (int off = 128; off > 0; off >>= 1) {
            if (t < off) {
                fb[t]       += fb[t + off];
                fb[256 + t] += fb[256 + t + off];
            }
            __syncthreads();
        }
        if (t == 0) {
            out[0] = fb[0] / (float)N_S
                   - (fb[256] / (float)N_S - logf((float)N_S));
            g_done = 0;                          // reset for next replay
        }
    }
}

// ---------------------------------------------------------------------------
extern "C" void kernel_launch(void* const* d_in, const int* in_sizes, int n_in,
                              void* d_out, int out_size) {
    const float* x  = (const float*)d_in[0];
    const float* y  = (const float*)d_in[1];
    const float* W1 = (const float*)d_in[2];
    const float* b1 = (const float*)d_in[3];
    const float* W2 = (const float*)d_in[4];
    const float* b2 = (const float*)d_in[5];

    cudaFuncSetAttribute(proj_kernel,
                         cudaFuncAttributeMaxDynamicSharedMemorySize,
                         PJ_SMEM_BYTES);

    proj_kernel<<<dim3(4, 32, 2), 256, PJ_SMEM_BYTES>>>(x, y, W1, b1);
    main_kernel<<<MAIN_CTAS, 256>>>(W2, b2, (float*)d_out);
}